// round 1
// baseline (speedup 1.0000x reference)
#include <cuda_runtime.h>
#include <math.h>

// MoE dims (fixed for this problem)
#define NT 16384   // tokens
#define DD 512     // model dim
#define HH 2048    // expert hidden
#define EE 8       // experts
#define KK 2       // top-k
#define RR (NT*KK) // routed rows total

// -------- device scratch (static: no allocation at launch time) --------
__device__ float g_h[(size_t)RR * HH];   // fc1 activations (256 MB)
__device__ float g_y[(size_t)RR * DD];   // fc2 outputs per routed row (64 MB)
__device__ int   g_perm[RR];             // routed row -> token
__device__ float g_gate[RR];             // routed row -> gate value
__device__ int   g_rowOf[NT * KK];       // (token,slot) -> routed row
__device__ int   g_topi[NT * KK];
__device__ float g_topv[NT * KK];
__device__ int   g_cnt[EE];
__device__ int   g_off[EE];
__device__ int   g_fill[EE];

// -------- kernel 0: reset per-launch counters --------
__global__ void zero_counts_kernel() {
    int i = threadIdx.x;
    if (i < EE) { g_cnt[i] = 0; g_fill[i] = 0; }
}

// -------- kernel 1: router (one warp per token) --------
__global__ __launch_bounds__(256)
void router_kernel(const float* __restrict__ x, const float* __restrict__ Wr) {
    __shared__ float sWrT[EE * DD];  // transposed [e][d] for conflict-free reads
    int tid = threadIdx.x;
    for (int i = tid; i < DD * EE; i += blockDim.x) {
        int d = i / EE, e = i % EE;
        sWrT[e * DD + d] = Wr[i];
    }
    __syncthreads();

    int warp = tid >> 5, lane = tid & 31;
    int n = blockIdx.x * (blockDim.x >> 5) + warp;
    if (n >= NT) return;

    float acc[EE];
#pragma unroll
    for (int e = 0; e < EE; e++) acc[e] = 0.f;

    const float* xr = x + (size_t)n * DD;
#pragma unroll
    for (int it = 0; it < DD / 32; it++) {
        float xv = xr[lane + it * 32];
#pragma unroll
        for (int e = 0; e < EE; e++) acc[e] += xv * sWrT[e * DD + lane + it * 32];
    }
#pragma unroll
    for (int e = 0; e < EE; e++) {
#pragma unroll
        for (int s = 16; s > 0; s >>= 1)
            acc[e] += __shfl_xor_sync(0xffffffffu, acc[e], s);
    }

    if (lane == 0) {
        float m = acc[0];
#pragma unroll
        for (int e = 1; e < EE; e++) m = fmaxf(m, acc[e]);
        float p[EE], s = 0.f;
#pragma unroll
        for (int e = 0; e < EE; e++) { p[e] = expf(acc[e] - m); s += p[e]; }
        float inv = 1.f / s;

        int i1 = 0; float v1 = p[0];
#pragma unroll
        for (int e = 1; e < EE; e++) if (p[e] > v1) { v1 = p[e]; i1 = e; }
        int i2 = -1; float v2 = -1.f;
#pragma unroll
        for (int e = 0; e < EE; e++) if (e != i1 && p[e] > v2) { v2 = p[e]; i2 = e; }

        g_topi[2 * n + 0] = i1; g_topv[2 * n + 0] = v1 * inv;
        g_topi[2 * n + 1] = i2; g_topv[2 * n + 1] = v2 * inv;
        atomicAdd(&g_cnt[i1], 1);
        atomicAdd(&g_cnt[i2], 1);
    }
}

// -------- kernel 2: exclusive prefix sum over 8 experts --------
__global__ void offsets_kernel() {
    if (threadIdx.x == 0) {
        int run = 0;
        for (int e = 0; e < EE; e++) { g_off[e] = run; run += g_cnt[e]; }
    }
}

// -------- kernel 3: scatter (token,slot) into expert-contiguous rows --------
__global__ void scatter_kernel() {
    int i = blockIdx.x * blockDim.x + threadIdx.x;
    if (i >= NT * KK) return;
    int token = i >> 1;
    int e = g_topi[i];
    int pos = atomicAdd(&g_fill[e], 1);
    int row = g_off[e] + pos;
    g_perm[row] = token;
    g_gate[row] = g_topv[i];
    g_rowOf[i] = row;
}

// -------- kernel 4: tiled fp32 SGEMM, 128x128 tile, 8x8 microtile --------
// FC1: C[rows,HH] = relu(gather(x) @ W1[e] + b1[e])   (Kdim=512, gather A rows)
// FC2: C[rows,DD] =        g_h      @ W2[e] + b2[e]   (Kdim=2048, contiguous A)
template <bool FC1>
__global__ __launch_bounds__(256, 2)
void gemm128_kernel(const float* __restrict__ X,
                    const float* __restrict__ Ball,
                    const float* __restrict__ bias) {
    constexpr int Kdim = FC1 ? DD : HH;
    constexpr int Ndim = FC1 ? HH : DD;

    const int e = blockIdx.z;
    const int cnt = g_cnt[e];
    const int m0 = blockIdx.y * 128;
    if (m0 >= cnt) return;
    const int off = g_off[e];
    const int n0 = blockIdx.x * 128;

    const float* __restrict__ Abase = FC1 ? X : (const float*)g_h;
    float* __restrict__ Cbase = FC1 ? g_h : g_y;
    const float* __restrict__ B = Ball + (size_t)e * Kdim * Ndim;

    __shared__ float As[8][128];
    __shared__ float Bs[8][128];
    __shared__ int sRow[128];  // A row start element offset, or -1 for pad rows

    const int tid = threadIdx.x;
    if (tid < 128) {
        int m = m0 + tid;
        int r = -1;
        if (m < cnt) {
            if (FC1) r = g_perm[off + m] * DD;
            else     r = (off + m) * Kdim;
        }
        sRow[tid] = r;
    }
    __syncthreads();

    const int am = tid >> 1;
    const int ak = (tid & 1) * 4;
    const int bk = tid >> 5;
    const int bn = (tid & 31) * 4;
    const int tm = (tid >> 4) * 8;
    const int tn = (tid & 15) * 8;

    float acc[8][8];
#pragma unroll
    for (int i = 0; i < 8; i++)
#pragma unroll
        for (int j = 0; j < 8; j++) acc[i][j] = 0.f;

    const int arow = sRow[am];

#pragma unroll 1
    for (int k0 = 0; k0 < Kdim; k0 += 8) {
        // stage A (gathered rows; zero-pad invalid rows)
        float4 av = make_float4(0.f, 0.f, 0.f, 0.f);
        if (arow >= 0) av = *(const float4*)(Abase + (size_t)arow + k0 + ak);
        As[ak + 0][am] = av.x; As[ak + 1][am] = av.y;
        As[ak + 2][am] = av.z; As[ak + 3][am] = av.w;
        // stage B
        float4 bv = *(const float4*)(B + (size_t)(k0 + bk) * Ndim + n0 + bn);
        *(float4*)&Bs[bk][bn] = bv;
        __syncthreads();

#pragma unroll
        for (int k = 0; k < 8; k++) {
            float4 a0 = *(const float4*)&As[k][tm];
            float4 a1 = *(const float4*)&As[k][tm + 4];
            float4 b0 = *(const float4*)&Bs[k][tn];
            float4 b1 = *(const float4*)&Bs[k][tn + 4];
            float a[8] = {a0.x, a0.y, a0.z, a0.w, a1.x, a1.y, a1.z, a1.w};
            float b[8] = {b0.x, b0.y, b0.z, b0.w, b1.x, b1.y, b1.z, b1.w};
#pragma unroll
            for (int i = 0; i < 8; i++)
#pragma unroll
                for (int j = 0; j < 8; j++)
                    acc[i][j] += a[i] * b[j];
        }
        __syncthreads();
    }

    // epilogue: +bias, optional relu, store to segment rows
    float bvv[8];
#pragma unroll
    for (int j = 0; j < 8; j++) bvv[j] = bias[(size_t)e * Ndim + n0 + tn + j];

#pragma unroll
    for (int i = 0; i < 8; i++) {
        int m = m0 + tm + i;
        if (m < cnt) {
            float* Cr = Cbase + (size_t)(off + m) * Ndim + n0 + tn;
#pragma unroll
            for (int j = 0; j < 8; j++) {
                float v = acc[i][j] + bvv[j];
                if (FC1) v = fmaxf(v, 0.f);
                Cr[j] = v;
            }
        }
    }
}

// -------- kernel 5: combine the two routed slots per token --------
__global__ __launch_bounds__(128)
void combine_kernel(float* __restrict__ out) {
    int n = blockIdx.x;
    int d = threadIdx.x * 4;
    int r0 = g_rowOf[2 * n + 0];
    int r1 = g_rowOf[2 * n + 1];
    float g0 = g_gate[r0];
    float g1 = g_gate[r1];
    float4 y0 = *(const float4*)&g_y[(size_t)r0 * DD + d];
    float4 y1 = *(const float4*)&g_y[(size_t)r1 * DD + d];
    float4 o;
    o.x = g0 * y0.x + g1 * y1.x;
    o.y = g0 * y0.y + g1 * y1.y;
    o.z = g0 * y0.z + g1 * y1.z;
    o.w = g0 * y0.w + g1 * y1.w;
    *(float4*)&out[(size_t)n * DD + d] = o;
}

// -------- kernel 6: zero any tail (e.g. scalar loss slot) --------
__global__ void tail_kernel(float* __restrict__ out, long long start, long long total) {
    long long i = start + (long long)blockIdx.x * blockDim.x + threadIdx.x;
    if (i < total) out[i] = 0.f;
}

extern "C" void kernel_launch(void* const* d_in, const int* in_sizes, int n_in,
                              void* d_out, int out_size) {
    const float* x  = (const float*)d_in[0];
    const float* Wr = (const float*)d_in[1];
    const float* W1 = (const float*)d_in[2];
    const float* b1 = (const float*)d_in[3];
    const float* W2 = (const float*)d_in[4];
    const float* b2 = (const float*)d_in[5];
    float* out = (float*)d_out;

    zero_counts_kernel<<<1, 32>>>();
    router_kernel<<<NT / 8, 256>>>(x, Wr);
    offsets_kernel<<<1, 1>>>();
    scatter_kernel<<<(NT * KK + 255) / 256, 256>>>();

    dim3 g1(HH / 128, NT / 128, EE);   // (16, 128, 8); most tiles early-exit
    gemm128_kernel<true><<<g1, 256>>>(x, W1, b1);

    dim3 g2(DD / 128, NT / 128, EE);   // (4, 128, 8)
    gemm128_kernel<false><<<g2, 256>>>(nullptr, W2, b2);

    combine_kernel<<<NT, 128>>>(out);

    long long main_elems = (long long)NT * DD;
    long long total = (long long)out_size;
    if (total > main_elems) {
        long long tail = total - main_elems;
        int blocks = (int)((tail + 255) / 256);
        tail_kernel<<<blocks, 256>>>(out, main_elems, total);
    }
}

// round 3
// speedup vs baseline: 2.6792x; 2.6792x over previous
#include <cuda_runtime.h>
#include <cuda_bf16.h>
#include <math.h>
#include <stdint.h>

// MoE dims (fixed)
#define NT 16384
#define DD 512
#define HH 2048
#define EE 8
#define KK 2
#define RR (NT*KK)

// ---------------- device scratch ----------------
__device__ __nv_bfloat16 g_x_hi[(size_t)NT * DD];
__device__ __nv_bfloat16 g_x_lo[(size_t)NT * DD];
__device__ __nv_bfloat16 g_w1t_hi[(size_t)EE * HH * DD];  // [e][h][d] K-major
__device__ __nv_bfloat16 g_w1t_lo[(size_t)EE * HH * DD];
__device__ __nv_bfloat16 g_w2t_hi[(size_t)EE * DD * HH];  // [e][d][h] K-major
__device__ __nv_bfloat16 g_w2t_lo[(size_t)EE * DD * HH];
__device__ __nv_bfloat16 g_h_hi[(size_t)RR * HH];
__device__ __nv_bfloat16 g_h_lo[(size_t)RR * HH];
__device__ float g_y[(size_t)RR * DD];
__device__ int   g_perm[RR];
__device__ int   g_rowOf[NT * KK];
__device__ float g_gate2[NT * KK];
__device__ int   g_topi[NT * KK];
__device__ float g_topv[NT * KK];
__device__ int   g_cnt[EE];
__device__ int   g_off[EE];
__device__ int   g_fill[EE];

__device__ __forceinline__ uint32_t smem_u32(const void* p) {
    uint32_t a;
    asm("{ .reg .u64 t; cvta.to.shared.u64 t, %1; cvt.u32.u64 %0, t; }" : "=r"(a) : "l"(p));
    return a;
}

__device__ __forceinline__ void cp16(uint32_t saddr, const void* gaddr, uint32_t sz) {
    asm volatile("cp.async.ca.shared.global [%0], [%1], 16, %2;"
                 :: "r"(saddr), "l"(gaddr), "r"(sz) : "memory");
}
#define CP_COMMIT() asm volatile("cp.async.commit_group;" ::: "memory")

__device__ __forceinline__ void ldsm_x4(uint32_t* r, uint32_t addr) {
    asm volatile("ldmatrix.sync.aligned.m8n8.x4.shared.b16 {%0,%1,%2,%3}, [%4];"
                 : "=r"(r[0]), "=r"(r[1]), "=r"(r[2]), "=r"(r[3]) : "r"(addr));
}

__device__ __forceinline__ void mma16816(float* c, const uint32_t* a, const uint32_t* b) {
    asm volatile(
        "mma.sync.aligned.m16n8k16.row.col.f32.bf16.bf16.f32 "
        "{%0,%1,%2,%3}, {%4,%5,%6,%7}, {%8,%9}, {%0,%1,%2,%3};"
        : "+f"(c[0]), "+f"(c[1]), "+f"(c[2]), "+f"(c[3])
        : "r"(a[0]), "r"(a[1]), "r"(a[2]), "r"(a[3]), "r"(b[0]), "r"(b[1]));
}

__device__ __forceinline__ void split_bf16(float v, __nv_bfloat16& hi, __nv_bfloat16& lo) {
    hi = __float2bfloat16(v);
    lo = __float2bfloat16(v - __bfloat162float(hi));
}

// ---------------- small kernels ----------------
__global__ void zero_counts_kernel() {
    int i = threadIdx.x;
    if (i < EE) { g_cnt[i] = 0; g_fill[i] = 0; }
}

__global__ __launch_bounds__(256)
void convert_x_kernel(const float* __restrict__ x) {
    int i = blockIdx.x * blockDim.x + threadIdx.x;
    if (i >= NT * DD / 4) return;
    float4 v = ((const float4*)x)[i];
    __nv_bfloat16 h0, h1, h2, h3, l0, l1, l2, l3;
    split_bf16(v.x, h0, l0); split_bf16(v.y, h1, l1);
    split_bf16(v.z, h2, l2); split_bf16(v.w, h3, l3);
    __nv_bfloat162* H = (__nv_bfloat162*)g_x_hi;
    __nv_bfloat162* L = (__nv_bfloat162*)g_x_lo;
    H[i * 2 + 0] = __nv_bfloat162(h0, h1); H[i * 2 + 1] = __nv_bfloat162(h2, h3);
    L[i * 2 + 0] = __nv_bfloat162(l0, l1); L[i * 2 + 1] = __nv_bfloat162(l2, l3);
}

// src: [E][R][C] fp32 -> dst: [E][C][R] bf16 hi/lo
template <bool ISW1>
__global__ __launch_bounds__(256)
void transpose_split_kernel(const float* __restrict__ src, int R, int C) {
    __shared__ float t[32][33];
    __nv_bfloat16* dH = ISW1 ? g_w1t_hi : g_w2t_hi;
    __nv_bfloat16* dL = ISW1 ? g_w1t_lo : g_w2t_lo;
    int e = blockIdx.z;
    int c0 = blockIdx.x * 32, r0 = blockIdx.y * 32;
    int tx = threadIdx.x, ty = threadIdx.y;
    const float* s = src + (size_t)e * R * C;
    __nv_bfloat16* dh = dH + (size_t)e * R * C;
    __nv_bfloat16* dl = dL + (size_t)e * R * C;
#pragma unroll
    for (int i = 0; i < 4; i++)
        t[ty + i * 8][tx] = s[(size_t)(r0 + ty + i * 8) * C + c0 + tx];
    __syncthreads();
#pragma unroll
    for (int i = 0; i < 4; i++) {
        float v = t[tx][ty + i * 8];
        __nv_bfloat16 hi, lo; split_bf16(v, hi, lo);
        size_t o = (size_t)(c0 + ty + i * 8) * R + r0 + tx;
        dh[o] = hi; dl[o] = lo;
    }
}

__global__ __launch_bounds__(256)
void router_kernel(const float* __restrict__ x, const float* __restrict__ Wr) {
    __shared__ float sWrT[EE * DD];
    int tid = threadIdx.x;
    for (int i = tid; i < DD * EE; i += blockDim.x) {
        int d = i / EE, e = i % EE;
        sWrT[e * DD + d] = Wr[i];
    }
    __syncthreads();
    int warp = tid >> 5, lane = tid & 31;
    int n = blockIdx.x * 8 + warp;
    if (n >= NT) return;
    float acc[EE];
#pragma unroll
    for (int e = 0; e < EE; e++) acc[e] = 0.f;
    const float* xr = x + (size_t)n * DD;
#pragma unroll
    for (int it = 0; it < DD / 32; it++) {
        float xv = xr[lane + it * 32];
#pragma unroll
        for (int e = 0; e < EE; e++) acc[e] += xv * sWrT[e * DD + lane + it * 32];
    }
#pragma unroll
    for (int e = 0; e < EE; e++)
#pragma unroll
        for (int s = 16; s > 0; s >>= 1)
            acc[e] += __shfl_xor_sync(0xffffffffu, acc[e], s);
    if (lane == 0) {
        float m = acc[0];
#pragma unroll
        for (int e = 1; e < EE; e++) m = fmaxf(m, acc[e]);
        float p[EE], s = 0.f;
#pragma unroll
        for (int e = 0; e < EE; e++) { p[e] = expf(acc[e] - m); s += p[e]; }
        float inv = 1.f / s;
        int i1 = 0; float v1 = p[0];
#pragma unroll
        for (int e = 1; e < EE; e++) if (p[e] > v1) { v1 = p[e]; i1 = e; }
        int i2 = -1; float v2 = -1.f;
#pragma unroll
        for (int e = 0; e < EE; e++) if (e != i1 && p[e] > v2) { v2 = p[e]; i2 = e; }
        g_topi[2 * n + 0] = i1; g_topv[2 * n + 0] = v1 * inv;
        g_topi[2 * n + 1] = i2; g_topv[2 * n + 1] = v2 * inv;
        atomicAdd(&g_cnt[i1], 1);
        atomicAdd(&g_cnt[i2], 1);
    }
}

__global__ void offsets_kernel() {
    if (threadIdx.x == 0) {
        int run = 0;
        for (int e = 0; e < EE; e++) { g_off[e] = run; run += g_cnt[e]; }
    }
}

__global__ void scatter_kernel() {
    int i = blockIdx.x * blockDim.x + threadIdx.x;
    if (i >= NT * KK) return;
    int token = i >> 1;
    int e = g_topi[i];
    int pos = atomicAdd(&g_fill[e], 1);
    int row = g_off[e] + pos;
    g_perm[row] = token;
    g_rowOf[i] = row;
    g_gate2[i] = g_topv[i];
}

// ---------------- HMMA GEMM: 128x128 tile, K chunks of 32, bf16 3-split ----------------
// smem per stage: Ahi/Alo/Bhi/Blo each [128][40] bf16 (80B row stride) = 40960B
#define ROWB 80
#define ARR_BYTES (128 * ROWB)
#define STAGE_BYTES (4 * ARR_BYTES)
#define SMEM_GEMM_BYTES (2 * STAGE_BYTES)

template <bool FC1>
__global__ __launch_bounds__(256)
void moe_gemm_hmma_kernel(const float* __restrict__ bias) {
    constexpr int Kd = FC1 ? DD : HH;
    constexpr int Nd = FC1 ? HH : DD;
    constexpr int NCHUNK = Kd / 32;

    extern __shared__ char smem[];
    const int e = blockIdx.z;
    const int cnt = g_cnt[e];
    const int m0 = blockIdx.y * 128;
    if (m0 >= cnt) return;
    const int off = g_off[e];
    const int n0 = blockIdx.x * 128;
    const int tid = threadIdx.x;
    const int wid = tid >> 5, lane = tid & 31;

    const __nv_bfloat16* aH = FC1 ? g_x_hi : g_h_hi;
    const __nv_bfloat16* aL = FC1 ? g_x_lo : g_h_lo;
    const __nv_bfloat16* wH = FC1 ? g_w1t_hi : g_w2t_hi;
    const __nv_bfloat16* wL = FC1 ? g_w1t_lo : g_w2t_lo;

    // ---- staging indices: thread -> (row, 2 of 4 16B segments) ----
    const int srow = tid >> 1;
    const int part = tid & 1;
    long long arow;   // element offset of gathered A row, -1 if pad
    {
        int m = m0 + srow;
        if (m < cnt) arow = FC1 ? (long long)g_perm[off + m] * DD
                                : (long long)(off + m) * HH;
        else arow = -1;
    }
    const size_t brow = ((size_t)e * Nd + n0 + srow) * Kd;

    const uint32_t sb = smem_u32(smem);
    const uint32_t sA_hi = sb;
    const uint32_t sA_lo = sb + ARR_BYTES;
    const uint32_t sB_hi = sb + 2 * ARR_BYTES;
    const uint32_t sB_lo = sb + 3 * ARR_BYTES;
    const uint32_t rowoff = srow * ROWB;

    auto stage = [&](int buf, int k0) {
        uint32_t so = buf * STAGE_BYTES + rowoff;
        uint32_t aok = (arow >= 0) ? 16u : 0u;
        const __nv_bfloat16* pah = aH + (arow >= 0 ? arow : 0) + k0;
        const __nv_bfloat16* pal = aL + (arow >= 0 ? arow : 0) + k0;
        const __nv_bfloat16* pbh = wH + brow + k0;
        const __nv_bfloat16* pbl = wL + brow + k0;
#pragma unroll
        for (int i = 0; i < 2; i++) {
            int s = part * 2 + i;            // segment 0..3 (16B each)
            cp16(sA_hi + so + s * 16, pah + s * 8, aok);
            cp16(sA_lo + so + s * 16, pal + s * 8, aok);
            cp16(sB_hi + so + s * 16, pbh + s * 8, 16u);
            cp16(sB_lo + so + s * 16, pbl + s * 8, 16u);
        }
        CP_COMMIT();
    };

    // ---- ldmatrix lane addressing ----
    const int warpM = (wid >> 2) * 64;       // 2 warp rows
    const int warpN = (wid & 3) * 32;        // 4 warp cols
    const int g = lane >> 3, lr = lane & 7;
    // A: group0: m0-7 k0 | g1: m8-15 k0 | g2: m0-7 k8 | g3: m8-15 k8
    const uint32_t aLaneOff = (uint32_t)(warpM + lr + ((g & 1) << 3)) * ROWB + ((g >> 1) << 4);
    // B: group0: n0-7 k0 | g1: n0-7 k8 | g2: n8-15 k0 | g3: n8-15 k8
    const uint32_t bLaneOff = (uint32_t)(warpN + lr + ((g >> 1) << 3)) * ROWB + ((g & 1) << 4);

    float acc[4][4][4];
#pragma unroll
    for (int i = 0; i < 4; i++)
#pragma unroll
        for (int j = 0; j < 4; j++)
#pragma unroll
            for (int k = 0; k < 4; k++) acc[i][j][k] = 0.f;

    stage(0, 0);
    if (NCHUNK > 1) stage(1, 32);

#pragma unroll 1
    for (int c = 0; c < NCHUNK; c++) {
        if (c + 1 < NCHUNK)
            asm volatile("cp.async.wait_group 1;" ::: "memory");
        else
            asm volatile("cp.async.wait_group 0;" ::: "memory");
        __syncthreads();

        const uint32_t st = (c & 1) * STAGE_BYTES;
#pragma unroll
        for (int ks = 0; ks < 2; ks++) {
            const uint32_t ko = ks * 32;
            uint32_t bh[4][4], bl[4][4];  // [pair of nfrags][4 regs] -> view below
            ldsm_x4(bh[0], sB_hi + st + ko + bLaneOff);
            ldsm_x4(bh[2], sB_hi + st + ko + bLaneOff + 16 * ROWB);
            ldsm_x4(bl[0], sB_lo + st + ko + bLaneOff);
            ldsm_x4(bl[2], sB_lo + st + ko + bLaneOff + 16 * ROWB);
            // regs r0,r1 = b0,b1 of nfrag(2t) ; r2,r3 = b0,b1 of nfrag(2t+1)
#pragma unroll
            for (int mt = 0; mt < 4; mt++) {
                uint32_t ah[4], al[4];
                ldsm_x4(ah, sA_hi + st + ko + aLaneOff + mt * 16 * ROWB);
                ldsm_x4(al, sA_lo + st + ko + aLaneOff + mt * 16 * ROWB);
#pragma unroll
                for (int nf = 0; nf < 4; nf++) {
                    const uint32_t* BH = &bh[(nf >> 1) * 2][(nf & 1) * 2];
                    const uint32_t* BL = &bl[(nf >> 1) * 2][(nf & 1) * 2];
                    mma16816(acc[mt][nf], ah, BH);
                    mma16816(acc[mt][nf], ah, BL);
                    mma16816(acc[mt][nf], al, BH);
                }
            }
        }
        __syncthreads();
        if (c + 2 < NCHUNK) stage(c & 1, (c + 2) * 32);
    }

    // ---- epilogue ----
    const int rr = lane >> 2;
    const int cc2 = (lane & 3) * 2;
#pragma unroll
    for (int mt = 0; mt < 4; mt++) {
#pragma unroll
        for (int nf = 0; nf < 4; nf++) {
            int col = n0 + warpN + nf * 8 + cc2;
            float bv0 = __ldg(&bias[(size_t)e * Nd + col]);
            float bv1 = __ldg(&bias[(size_t)e * Nd + col + 1]);
#pragma unroll
            for (int h = 0; h < 2; h++) {
                int m = m0 + warpM + mt * 16 + rr + h * 8;
                if (m < cnt) {
                    float v0 = acc[mt][nf][h * 2 + 0] + bv0;
                    float v1 = acc[mt][nf][h * 2 + 1] + bv1;
                    size_t orow = (size_t)(off + m);
                    if (FC1) {
                        v0 = fmaxf(v0, 0.f); v1 = fmaxf(v1, 0.f);
                        __nv_bfloat16 h0, l0, h1, l1;
                        split_bf16(v0, h0, l0); split_bf16(v1, h1, l1);
                        *(__nv_bfloat162*)(g_h_hi + orow * HH + col) = __nv_bfloat162(h0, h1);
                        *(__nv_bfloat162*)(g_h_lo + orow * HH + col) = __nv_bfloat162(l0, l1);
                    } else {
                        *(float2*)(g_y + orow * DD + col) = make_float2(v0, v1);
                    }
                }
            }
        }
    }
}

// ---------------- combine ----------------
__global__ __launch_bounds__(128)
void combine_kernel(float* __restrict__ out) {
    int n = blockIdx.x;
    int d = threadIdx.x * 4;
    int r0 = g_rowOf[2 * n + 0];
    int r1 = g_rowOf[2 * n + 1];
    float g0 = g_gate2[2 * n + 0];
    float g1 = g_gate2[2 * n + 1];
    float4 y0 = *(const float4*)&g_y[(size_t)r0 * DD + d];
    float4 y1 = *(const float4*)&g_y[(size_t)r1 * DD + d];
    float4 o;
    o.x = g0 * y0.x + g1 * y1.x;
    o.y = g0 * y0.y + g1 * y1.y;
    o.z = g0 * y0.z + g1 * y1.z;
    o.w = g0 * y0.w + g1 * y1.w;
    *(float4*)&out[(size_t)n * DD + d] = o;
}

__global__ void tail_kernel(float* __restrict__ out, long long start, long long total) {
    long long i = start + (long long)blockIdx.x * blockDim.x + threadIdx.x;
    if (i < total) out[i] = 0.f;
}

extern "C" void kernel_launch(void* const* d_in, const int* in_sizes, int n_in,
                              void* d_out, int out_size) {
    const float* x  = (const float*)d_in[0];
    const float* Wr = (const float*)d_in[1];
    const float* W1 = (const float*)d_in[2];
    const float* b1 = (const float*)d_in[3];
    const float* W2 = (const float*)d_in[4];
    const float* b2 = (const float*)d_in[5];
    float* out = (float*)d_out;

    cudaFuncSetAttribute(moe_gemm_hmma_kernel<true>,
                         cudaFuncAttributeMaxDynamicSharedMemorySize, SMEM_GEMM_BYTES);
    cudaFuncSetAttribute(moe_gemm_hmma_kernel<false>,
                         cudaFuncAttributeMaxDynamicSharedMemorySize, SMEM_GEMM_BYTES);

    zero_counts_kernel<<<1, 32>>>();
    convert_x_kernel<<<(NT * DD / 4 + 255) / 256, 256>>>(x);
    transpose_split_kernel<true ><<<dim3(HH / 32, DD / 32, EE), dim3(32, 8)>>>(W1, DD, HH);
    transpose_split_kernel<false><<<dim3(DD / 32, HH / 32, EE), dim3(32, 8)>>>(W2, HH, DD);
    router_kernel<<<NT / 8, 256>>>(x, Wr);
    offsets_kernel<<<1, 1>>>();
    scatter_kernel<<<(NT * KK + 255) / 256, 256>>>();

    moe_gemm_hmma_kernel<true ><<<dim3(HH / 128, NT / 128, EE), 256, SMEM_GEMM_BYTES>>>(b1);
    moe_gemm_hmma_kernel<false><<<dim3(DD / 128, NT / 128, EE), 256, SMEM_GEMM_BYTES>>>(b2);

    combine_kernel<<<NT, 128>>>(out);

    long long main_elems = (long long)NT * DD;
    long long total = (long long)out_size;
    if (total > main_elems) {
        long long tail = total - main_elems;
        int blocks = (int)((tail + 255) / 256);
        tail_kernel<<<blocks, 256>>>(out, main_elems, total);
    }
}